// round 2
// baseline (speedup 1.0000x reference)
#include <cuda_runtime.h>

// Model: 2-layer GRU LM.
//   x[B,T] -> emb gather [B,T,E] -> GRU0 -> GRU1 -> FC(32) + ReLU -> [B*T, 32]
// B=64, T=2048, E=H=128, 3H=384, C=32.
//
// Plan:
//   1) gates_gemm (gather):  gi0[t,b,g] = emb[x[b,t]] . w_ih0[g] + b_ih0[g]
//   2) gru_kernel layer 0:   1 CTA per batch element, W_hh rows in registers
//   3) gates_gemm (plain):   gi1 = y0 . w_ih1^T + b_ih1
//   4) gru_kernel layer 1
//   5) fc_kernel:            out = relu(y1 . fc_w^T + fc_b), reordered to [B*T, C]

#define BSZ  64
#define TSZ  2048
#define EDIM 128
#define HDIM 128
#define G3   384
#define CDIM 32
#define MTOK (BSZ * TSZ)   // 131072 tokens

// Scratch (static device globals: allocation-free).
__device__ float g_gi[(size_t)MTOK * G3];    // 50,331,648 floats (~201 MB)
__device__ float g_y0[(size_t)MTOK * HDIM];  // ~67 MB
__device__ float g_y1[(size_t)MTOK * HDIM];  // ~67 MB

__device__ __forceinline__ float sigm(float x) {
    return 1.0f / (1.0f + __expf(-x));
}
__device__ __forceinline__ float tanh_acc(float x) {
    // exact algebra, MUFU-backed exp; clamp so exp never overflows
    float xc = fminf(fmaxf(x, -44.0f), 44.0f);
    float e = __expf(-2.0f * xc);
    return (1.0f - e) / (1.0f + e);
}

// ---------------------------------------------------------------------------
// GEMM for input gates: C[M=131072, N=384] = A[M,128] @ W^T + b
// A row m is either emb[x[b,t]] (gather=1, m = t*B + b) or arows[m] (gather=0).
// Tile 64x64, K staged in two 64-chunks, 256 threads, 4x4 micro-tile.
// ---------------------------------------------------------------------------
__global__ __launch_bounds__(256, 2) void gates_gemm(
    const float* __restrict__ arows,   // [M,128] when gather==0
    const int*   __restrict__ xids,    // [B,T]   when gather==1
    const float* __restrict__ emb,     // [V,128] when gather==1
    const float* __restrict__ wih,     // [384,128]
    const float* __restrict__ bih,     // [384]
    float* __restrict__ gi,            // [M,384]
    int gather)
{
    __shared__ __align__(16) float As[64][64];  // [k][m]
    __shared__ __align__(16) float Ws[64][64];  // [k][n]

    const int tid = threadIdx.x;
    const int bm = blockIdx.x, bn = blockIdx.y;
    const int tx = tid & 15, ty = tid >> 4;
    const int mloc = tid & 63;    // which row of the tile this thread loads
    const int kq   = tid >> 6;    // which k-quarter (0..3) of the chunk

    const int mg = bm * 64 + mloc;
    const float* arow;
    if (gather) {
        const int bb = mg & (BSZ - 1);
        const int tt = mg >> 6;
        const int tok = xids[bb * TSZ + tt];
        arow = emb + (size_t)tok * EDIM;
    } else {
        arow = arows + (size_t)mg * EDIM;
    }
    const float* wrow = wih + (size_t)(bn * 64 + mloc) * EDIM;

    float acc[4][4];
#pragma unroll
    for (int i = 0; i < 4; i++)
#pragma unroll
        for (int j = 0; j < 4; j++) acc[i][j] = 0.0f;

    for (int kk = 0; kk < EDIM; kk += 64) {
#pragma unroll
        for (int j = 0; j < 4; j++) {
            const int k0 = kq * 16 + j * 4;
            float4 a = *reinterpret_cast<const float4*>(arow + kk + k0);
            As[k0 + 0][mloc] = a.x;
            As[k0 + 1][mloc] = a.y;
            As[k0 + 2][mloc] = a.z;
            As[k0 + 3][mloc] = a.w;
            float4 w = *reinterpret_cast<const float4*>(wrow + kk + k0);
            Ws[k0 + 0][mloc] = w.x;
            Ws[k0 + 1][mloc] = w.y;
            Ws[k0 + 2][mloc] = w.z;
            Ws[k0 + 3][mloc] = w.w;
        }
        __syncthreads();
#pragma unroll
        for (int k = 0; k < 64; k++) {
            float4 a4 = *reinterpret_cast<const float4*>(&As[k][ty * 4]);
            float4 w4 = *reinterpret_cast<const float4*>(&Ws[k][tx * 4]);
            acc[0][0] = fmaf(a4.x, w4.x, acc[0][0]);
            acc[0][1] = fmaf(a4.x, w4.y, acc[0][1]);
            acc[0][2] = fmaf(a4.x, w4.z, acc[0][2]);
            acc[0][3] = fmaf(a4.x, w4.w, acc[0][3]);
            acc[1][0] = fmaf(a4.y, w4.x, acc[1][0]);
            acc[1][1] = fmaf(a4.y, w4.y, acc[1][1]);
            acc[1][2] = fmaf(a4.y, w4.z, acc[1][2]);
            acc[1][3] = fmaf(a4.y, w4.w, acc[1][3]);
            acc[2][0] = fmaf(a4.z, w4.x, acc[2][0]);
            acc[2][1] = fmaf(a4.z, w4.y, acc[2][1]);
            acc[2][2] = fmaf(a4.z, w4.z, acc[2][2]);
            acc[2][3] = fmaf(a4.z, w4.w, acc[2][3]);
            acc[3][0] = fmaf(a4.w, w4.x, acc[3][0]);
            acc[3][1] = fmaf(a4.w, w4.y, acc[3][1]);
            acc[3][2] = fmaf(a4.w, w4.z, acc[3][2]);
            acc[3][3] = fmaf(a4.w, w4.w, acc[3][3]);
        }
        __syncthreads();
    }

    float4 b4 = *reinterpret_cast<const float4*>(bih + bn * 64 + tx * 4);
#pragma unroll
    for (int i = 0; i < 4; i++) {
        const int row = bm * 64 + ty * 4 + i;
        float4 o;
        o.x = acc[i][0] + b4.x;
        o.y = acc[i][1] + b4.y;
        o.z = acc[i][2] + b4.z;
        o.w = acc[i][3] + b4.w;
        *reinterpret_cast<float4*>(gi + (size_t)row * G3 + bn * 64 + tx * 4) = o;
    }
}

// ---------------------------------------------------------------------------
// GRU recurrence: 1 CTA per batch element, 384 threads.
// Thread g owns row g of W_hh (128 floats in registers).
// Per step: gh = W_hh @ h (+b_hh) via register FMA with h broadcast from smem,
// then 128 "updater" threads apply the gate nonlinearities.
// gi layout: [T, B, 3H] so per-step reads are contiguous per CTA.
// y layout:  [T, B, H].
// ---------------------------------------------------------------------------
__global__ __launch_bounds__(384, 1) void gru_kernel(
    const float* __restrict__ gi,   // [T,B,384], includes b_ih
    const float* __restrict__ whh,  // [384,128]
    const float* __restrict__ bhh,  // [384]
    float* __restrict__ y)          // [T,B,128]
{
    __shared__ __align__(16) float h_s[HDIM];
    __shared__ __align__(16) float gh_s[G3];

    const int b = blockIdx.x;
    const int g = threadIdx.x;

    // W_hh row -> registers
    float4 w4[32];
    const float4* wrow = reinterpret_cast<const float4*>(whh + (size_t)g * HDIM);
#pragma unroll
    for (int i = 0; i < 32; i++) w4[i] = wrow[i];
    const float bias = bhh[g];

    if (g < HDIM) h_s[g] = 0.0f;
    __syncthreads();

#pragma unroll 1
    for (int t = 0; t < TSZ; t++) {
        const float* gp = gi + ((size_t)t * BSZ + b) * G3;
        float gr = 0.0f, gz = 0.0f, gn = 0.0f;
        if (g < HDIM) {  // issue early; consumed ~1000 cycles later
            gr = __ldg(gp + g);
            gz = __ldg(gp + g + HDIM);
            gn = __ldg(gp + g + 2 * HDIM);
        }

        float acc = bias;
        const float4* h4 = reinterpret_cast<const float4*>(h_s);
#pragma unroll
        for (int k = 0; k < 32; k++) {
            float4 hv = h4[k];
            acc = fmaf(w4[k].x, hv.x, acc);
            acc = fmaf(w4[k].y, hv.y, acc);
            acc = fmaf(w4[k].z, hv.z, acc);
            acc = fmaf(w4[k].w, hv.w, acc);
        }
        gh_s[g] = acc;
        __syncthreads();  // gh_s complete; also all h_s reads done

        if (g < HDIM) {
            const float r = sigm(gr + acc);               // acc == gh_s[g] (r rows)
            const float z = sigm(gz + gh_s[g + HDIM]);
            const float n = tanh_acc(gn + r * gh_s[g + 2 * HDIM]);
            const float hnew = (1.0f - z) * n + z * h_s[g];
            h_s[g] = hnew;
            y[((size_t)t * BSZ + b) * HDIM + g] = hnew;
        }
        __syncthreads();  // h_s updated & gh_s consumed before next step
    }
}

// ---------------------------------------------------------------------------
// FC head: out[b*T+t, c] = relu(y1[t,b,:] . fc_w[c] + fc_b[c])
// 32 tokens per block; thread = (token group of 4, class c).
// ---------------------------------------------------------------------------
__global__ __launch_bounds__(256, 2) void fc_kernel(
    const float* __restrict__ y,    // [T,B,128]
    const float* __restrict__ fcw,  // [32,128]
    const float* __restrict__ fcb,  // [32]
    float* __restrict__ out)        // [B*T,32]
{
    __shared__ float ws[CDIM][HDIM + 1];          // +1 pad -> conflict-free
    __shared__ __align__(16) float ys[32][HDIM];

    const int tid = threadIdx.x;
    const size_t m0 = (size_t)blockIdx.x * 32;

    for (int i = tid; i < CDIM * (HDIM / 4); i += 256) {
        const int c = i / (HDIM / 4);
        const int k4 = i % (HDIM / 4);
        float4 w = reinterpret_cast<const float4*>(fcw)[(size_t)c * (HDIM / 4) + k4];
        ws[c][k4 * 4 + 0] = w.x;
        ws[c][k4 * 4 + 1] = w.y;
        ws[c][k4 * 4 + 2] = w.z;
        ws[c][k4 * 4 + 3] = w.w;
    }
    for (int i = tid; i < 32 * (HDIM / 4); i += 256) {
        const int tl = i / (HDIM / 4);
        const int k4 = i % (HDIM / 4);
        float4 v = reinterpret_cast<const float4*>(y + (m0 + tl) * HDIM)[k4];
        *reinterpret_cast<float4*>(&ys[tl][k4 * 4]) = v;
    }
    __syncthreads();

    const int c = tid & 31;
    const int t0 = (tid >> 5) * 4;
    const float bias = fcb[c];
    float a0 = bias, a1 = bias, a2 = bias, a3 = bias;
#pragma unroll
    for (int k = 0; k < HDIM; k++) {
        const float w = ws[c][k];
        a0 = fmaf(w, ys[t0 + 0][k], a0);
        a1 = fmaf(w, ys[t0 + 1][k], a1);
        a2 = fmaf(w, ys[t0 + 2][k], a2);
        a3 = fmaf(w, ys[t0 + 3][k], a3);
    }
    float r[4] = {a0, a1, a2, a3};
#pragma unroll
    for (int q = 0; q < 4; q++) {
        const size_t m = m0 + t0 + q;          // m = t*B + b
        const int bidx = (int)(m & 63);
        const int tt = (int)(m >> 6);
        out[((size_t)bidx * TSZ + tt) * CDIM + c] = fmaxf(r[q], 0.0f);
    }
}

extern "C" void kernel_launch(void* const* d_in, const int* in_sizes, int n_in,
                              void* d_out, int out_size) {
    const int*   x     = (const int*)  d_in[0];
    const float* emb   = (const float*)d_in[1];
    const float* w_ih0 = (const float*)d_in[2];
    const float* w_hh0 = (const float*)d_in[3];
    const float* b_ih0 = (const float*)d_in[4];
    const float* b_hh0 = (const float*)d_in[5];
    const float* w_ih1 = (const float*)d_in[6];
    const float* w_hh1 = (const float*)d_in[7];
    const float* b_ih1 = (const float*)d_in[8];
    const float* b_hh1 = (const float*)d_in[9];
    const float* fc_w  = (const float*)d_in[10];
    const float* fc_b  = (const float*)d_in[11];
    float* out = (float*)d_out;

    float *gi, *y0, *y1;
    cudaGetSymbolAddress((void**)&gi, g_gi);
    cudaGetSymbolAddress((void**)&y0, g_y0);
    cudaGetSymbolAddress((void**)&y1, g_y1);

    dim3 ggrid(MTOK / 64, G3 / 64);
    gates_gemm<<<ggrid, 256>>>(nullptr, x, emb, w_ih0, b_ih0, gi, 1);
    gru_kernel<<<BSZ, 384>>>(gi, w_hh0, b_hh0, y0);
    gates_gemm<<<ggrid, 256>>>(y0, nullptr, nullptr, w_ih1, b_ih1, gi, 0);
    gru_kernel<<<BSZ, 384>>>(gi, w_hh1, b_hh1, y1);
    fc_kernel<<<MTOK / 32, 256>>>(y1, fc_w, fc_b, out);
}